// round 15
// baseline (speedup 1.0000x reference)
#include <cuda_runtime.h>
#include <cuda_fp16.h>
#include <cstdint>

#define MTOT 8192
#define DM   1024
#define DF   4096
#define NH   8

#define LDS_   72                        // smem row stride (elems), 144B
#define SLOT_  (128*LDS_)                // one 128x64 tile (elems)
#define SMEM_BYTES (6*SLOT_*2)           // 3 A slots + 3 B slots = 110592

static __device__ __align__(256) __half g_Xs  [(size_t)MTOT*DM];      // x rounded to fp16
static __device__ __align__(256) __half g_Wis [(size_t)DM*DM];
static __device__ __align__(256) __half g_W1s [(size_t)NH*DF*DM];
static __device__ __align__(256) __half g_W2s [(size_t)NH*DM*DF];
static __device__ __align__(256) __half g_Hid [(size_t)MTOT*NH*DF];   // [t][h*DF+c], w-weighted
static __device__ __align__(256) float g_gcomb[(size_t)MTOT*DM];
static __device__ __align__(256) float g_rsproj[4*DM];
static __device__ __align__(256) float g_wts[MTOT*NH];

// ---------------- helpers ----------------
__device__ __forceinline__ uint32_t smem_u32(const void* p){
    uint32_t a;
    asm("{ .reg .u64 t; cvta.to.shared.u64 t, %1; cvt.u32.u64 %0, t; }" : "=r"(a) : "l"(p));
    return a;
}
__device__ __forceinline__ float gelu_f(float v){
    return 0.5f * v * (1.0f + erff(v * 0.7071067811865476f));
}
__device__ __forceinline__ void ldm4(uint32_t* r, uint32_t addr){
    asm volatile("ldmatrix.sync.aligned.m8n8.x4.shared.b16 {%0,%1,%2,%3}, [%4];"
                 : "=r"(r[0]), "=r"(r[1]), "=r"(r[2]), "=r"(r[3]) : "r"(addr));
}
__device__ __forceinline__ void mma_f16(float* d, const uint32_t* a, uint32_t b0, uint32_t b1){
    asm volatile("mma.sync.aligned.m16n8k16.row.col.f32.f16.f16.f32 "
                 "{%0,%1,%2,%3}, {%4,%5,%6,%7}, {%8,%9}, {%0,%1,%2,%3};"
                 : "+f"(d[0]), "+f"(d[1]), "+f"(d[2]), "+f"(d[3])
                 : "r"(a[0]), "r"(a[1]), "r"(a[2]), "r"(a[3]), "r"(b0), "r"(b1));
}
#define CP16(dst, src) asm volatile("cp.async.cg.shared.global [%0], [%1], 16;" :: "r"(dst), "l"(src))
#define CP_COMMIT()    asm volatile("cp.async.commit_group;")
#define CP_WAIT1()     asm volatile("cp.async.wait_group 1;" ::: "memory")

// ---------------- prep kernels ----------------
__global__ void round_x_kernel(const float* __restrict__ x){
    const int t = blockIdx.x;
    const float* xr = x + (size_t)t*DM;
    __half* o = g_Xs + (size_t)t*DM;
    for (int k = threadIdx.x; k < DM; k += 256)
        o[k] = __float2half_rn(xr[k]);
}

__global__ void transpose_h_kernel(const float* __restrict__ W, __half* __restrict__ Ws,
                                   int K, int N, size_t inStride, size_t outStride){
    __shared__ float tile[32][33];
    const float* Wm = W + inStride * blockIdx.z;
    __half* Om = Ws + outStride * blockIdx.z;
    const int n0 = blockIdx.x*32, k0 = blockIdx.y*32;
    for (int i = threadIdx.y; i < 32; i += 8)
        tile[i][threadIdx.x] = Wm[(size_t)(k0+i)*N + n0 + threadIdx.x];
    __syncthreads();
    for (int i = threadIdx.y; i < 32; i += 8){
        const int n = n0 + i, k = k0 + threadIdx.x;
        Om[(size_t)n*K + k] = __float2half_rn(tile[threadIdx.x][i]);
    }
}

__global__ void rsproj_kernel(const float* __restrict__ rs, const float* __restrict__ Wsm,
                              const float* __restrict__ bs){
    __shared__ float srs[DM];
    const int b = blockIdx.x;
    const int n = blockIdx.y*128 + threadIdx.x;
    for (int i = threadIdx.x; i < DM; i += 128) srs[i] = rs[(size_t)b*DM + i];
    __syncthreads();
    float acc = bs[n];
    for (int k = 0; k < DM; k++) acc = fmaf(srs[k], Wsm[(size_t)k*DM + n], acc);
    g_rsproj[b*DM + n] = acc;
}

__global__ void logits_kernel(const float* __restrict__ Wg, const float* __restrict__ bg,
                              float* __restrict__ wout){
    __shared__ float sW[NH][DM];
    const int tid = threadIdx.x;
    for (int i = tid; i < DM*NH; i += 256) sW[i & (NH-1)][i >> 3] = Wg[i];
    __syncthreads();
    const int warp = tid >> 5, lid = tid & 31;
    const int t = blockIdx.x*8 + warp;
    const float* g = g_gcomb + (size_t)t*DM;
    float a[NH];
    #pragma unroll
    for (int h = 0; h < NH; h++) a[h] = 0.f;
    for (int k = lid; k < DM; k += 32){
        const float gv = g[k];
        #pragma unroll
        for (int h = 0; h < NH; h++) a[h] = fmaf(gv, sW[h][k], a[h]);
    }
    #pragma unroll
    for (int h = 0; h < NH; h++)
        #pragma unroll
        for (int o = 16; o > 0; o >>= 1)
            a[h] += __shfl_xor_sync(0xFFFFFFFFu, a[h], o);
    if (lid == 0){
        float mx = -1e30f;
        #pragma unroll
        for (int h = 0; h < NH; h++){ a[h] += bg[h]; mx = fmaxf(mx, a[h]); }
        float s = 0.f;
        #pragma unroll
        for (int h = 0; h < NH; h++){ a[h] = expf(a[h]-mx); s += a[h]; }
        const float inv = 1.f/s;
        #pragma unroll
        for (int h = 0; h < NH; h++){
            const float w = a[h]*inv;
            g_wts[t*NH + h] = w;
            wout[t*NH + h]  = w;
        }
    }
}

// ---------------- GEMM: 128x128 CTA tile, 8 warps (2m x 4n), 64x32 warp tile ----------------
// Plain fp16 GEMM: D[m,n] = sum_k A[m,k]*B[n,k], both K-major.
// kk-level fragment double-buffering: ldmatrix for kk+1 issued before MMAs of kk.
// EPI 0: gelu(acc + bi[c] + rsproj) -> g_gcomb.                 grid (8, 64)
// EPI 1: w[t,z]*gelu(acc + b1[z,c]) -> fp16 g_Hid[t][z*DF+c].   grid (32, 64, 8)
// EPI 2: acc + sum_h w[t,h]*b2[h,c] -> out; A = g_Hid (K=32768). grid (8, 64)
template<int EPI>
__global__ __launch_bounds__(256)
void mma_kernel(const __half* __restrict__ A,
                const __half* __restrict__ B,
                const float* __restrict__ bias,
                const float* __restrict__ extra,
                float* __restrict__ outF,
                __half* __restrict__ outS)
{
    constexpr int RSA = (EPI == 2) ? NH*DF : DM;      // A row stride (elems)
    constexpr int RSB = (EPI == 2) ? DF    : DM;      // B row stride (elems)
    constexpr int NCH = (EPI == 2) ? (NH*DF/64) : (DM/64);   // 512 or 16

    extern __shared__ __align__(16) __half sm[];
    __half* smA = sm;                     // 3 slots
    __half* smB = sm + 3*SLOT_;           // 3 slots

    const int tid = threadIdx.x;
    const int wid = tid >> 5, lane = tid & 31;
    const int wm = wid >> 2, wn = wid & 3;
    const int m0 = blockIdx.y * 128, n0 = blockIdx.x * 128;
    const int z  = blockIdx.z;

    const __half* Bk = B;
    const float*  biask = bias;
    if (EPI == 1){
        Bk    = B + (size_t)z * DF * DM;
        biask = bias + (size_t)z * DF;
    }

    const int grow = tid >> 3;          // 0..31
    const int gcol = (tid & 7) * 8;     // 0,8,...,56

    float acc[4][4][4];
    #pragma unroll
    for (int i = 0; i < 4; i++)
        #pragma unroll
        for (int j = 0; j < 4; j++)
            #pragma unroll
            for (int r = 0; r < 4; r++) acc[i][j][r] = 0.f;

    auto load_stage = [&](int kc){
        __half* sa = smA + (kc % 3) * SLOT_;
        __half* sb = smB + (kc % 3) * SLOT_;
        const size_t koA = (size_t)kc * 64;
        size_t baseB;
        if (EPI == 2){
            const int hB = kc >> 6;                   // DF/64 = 64 chunks/head
            baseB = (size_t)hB * DM * DF + (size_t)(kc & 63) * 64;
        } else {
            baseB = (size_t)kc * 64;
        }
        #pragma unroll
        for (int r = 0; r < 4; r++){
            const int row = grow + r*32;
            CP16(smem_u32(sa + (size_t)row*LDS_ + gcol),
                 A + (size_t)(m0 + row)*RSA + koA + gcol);
            CP16(smem_u32(sb + (size_t)row*LDS_ + gcol),
                 Bk + baseB + (size_t)(n0 + row)*RSB + gcol);
        }
        CP_COMMIT();
    };

    load_stage(0);
    load_stage(1);

    for (int kc = 0; kc < NCH; kc++){
        CP_WAIT1();
        __syncthreads();
        const __half* sa = smA + (kc % 3) * SLOT_;
        const __half* sb = smB + (kc % 3) * SLOT_;
        const uint32_t abase = smem_u32(sa + ((size_t)(wm*64 + (lane & 15)))*LDS_ + (lane >> 4)*8);
        const uint32_t bbase = smem_u32(sb + ((size_t)(wn*32 + (lane & 15)))*LDS_ + (lane >> 4)*8);

        uint32_t af[2][4][4], bf[2][2][4];
        #pragma unroll
        for (int mt = 0; mt < 4; mt++)
            ldm4(af[0][mt], abase + (uint32_t)(mt*16*LDS_)*2);
        #pragma unroll
        for (int g = 0; g < 2; g++)
            ldm4(bf[0][g], bbase + (uint32_t)(g*16*LDS_)*2);

        #pragma unroll
        for (int kk = 0; kk < 4; kk++){
            const int cur = kk & 1, nxt = cur ^ 1;
            if (kk < 3){
                #pragma unroll
                for (int mt = 0; mt < 4; mt++)
                    ldm4(af[nxt][mt], abase + (uint32_t)(mt*16*LDS_)*2 + (kk+1)*32);
                #pragma unroll
                for (int g = 0; g < 2; g++)
                    ldm4(bf[nxt][g], bbase + (uint32_t)(g*16*LDS_)*2 + (kk+1)*32);
            }
            #pragma unroll
            for (int mt = 0; mt < 4; mt++)
                #pragma unroll
                for (int nt = 0; nt < 4; nt++)
                    mma_f16(acc[mt][nt], af[cur][mt],
                            bf[cur][nt>>1][nt&1], bf[cur][nt>>1][2 + (nt&1)]);
        }
        if (kc + 2 < NCH) load_stage(kc + 2);
        else CP_COMMIT();
    }

    // EPI2: stage b2[8][128-block] into (now free) SMEM
    float* sB2 = (float*)sm;
    if (EPI == 2){
        __syncthreads();
        for (int i = tid; i < NH*128; i += 256)
            sB2[i] = bias[(i >> 7)*DM + n0 + (i & 127)];
        __syncthreads();
    }

    // -------- epilogue --------
    const int lr = lane >> 2, lc = 2 * (lane & 3);
    #pragma unroll
    for (int mt = 0; mt < 4; mt++){
        #pragma unroll
        for (int half = 0; half < 2; half++){
            const int t = m0 + wm*64 + mt*16 + lr + 8*half;
            float wv[NH];
            if (EPI == 2){
                const float* wr = extra + t*NH;
                #pragma unroll
                for (int h = 0; h < NH; h++) wv[h] = wr[h];
            }
            float gw = 0.f;
            if (EPI == 1) gw = extra[t*NH + z];
            #pragma unroll
            for (int nt = 0; nt < 4; nt++){
                const int c = n0 + wn*32 + nt*8 + lc;
                float v0 = acc[mt][nt][2*half];
                float v1 = acc[mt][nt][2*half + 1];
                if (EPI == 0){
                    const float* rp = extra + (size_t)(t >> 11)*DM;
                    float2 o;
                    o.x = gelu_f(v0 + biask[c]   + rp[c]);
                    o.y = gelu_f(v1 + biask[c+1] + rp[c+1]);
                    *reinterpret_cast<float2*>(outF + (size_t)t*DM + c) = o;
                } else if (EPI == 1){
                    v0 = gw * gelu_f(v0 + biask[c]);
                    v1 = gw * gelu_f(v1 + biask[c+1]);
                    __half2 ph;
                    ph.x = __float2half_rn(v0); ph.y = __float2half_rn(v1);
                    *reinterpret_cast<__half2*>(outS + (size_t)t*NH*DF + (size_t)z*DF + c) = ph;
                } else {
                    const int cl = c - n0;
                    float b0 = 0.f, b1v = 0.f;
                    #pragma unroll
                    for (int h = 0; h < NH; h++){
                        b0  = fmaf(wv[h], sB2[h*128 + cl],     b0);
                        b1v = fmaf(wv[h], sB2[h*128 + cl + 1], b1v);
                    }
                    float2 o; o.x = v0 + b0; o.y = v1 + b1v;
                    *reinterpret_cast<float2*>(outF + (size_t)t*DM + c) = o;
                }
            }
        }
    }
}

// ---------------- host ----------------
extern "C" void kernel_launch(void* const* d_in, const int* in_sizes, int n_in,
                              void* d_out, int out_size){
    const float* x   = (const float*)d_in[0];
    const float* rs  = (const float*)d_in[1];
    const float* W1  = (const float*)d_in[2];
    const float* b1  = (const float*)d_in[3];
    const float* W2  = (const float*)d_in[4];
    const float* b2  = (const float*)d_in[5];
    const float* Wsm = (const float*)d_in[6];
    const float* bs  = (const float*)d_in[7];
    const float* Wi  = (const float*)d_in[8];
    const float* bi  = (const float*)d_in[9];
    const float* Wg  = (const float*)d_in[10];
    const float* bg  = (const float*)d_in[11];
    float* out = (float*)d_out;

    void *pXs,*pWis,*pW1s,*pW2s,*pHid,*pGc,*pRp,*pWts;
    cudaGetSymbolAddress(&pXs,  g_Xs);
    cudaGetSymbolAddress(&pWis, g_Wis);
    cudaGetSymbolAddress(&pW1s, g_W1s);
    cudaGetSymbolAddress(&pW2s, g_W2s);
    cudaGetSymbolAddress(&pHid, g_Hid);
    cudaGetSymbolAddress(&pGc,  g_gcomb);
    cudaGetSymbolAddress(&pRp,  g_rsproj);
    cudaGetSymbolAddress(&pWts, g_wts);

    cudaFuncSetAttribute(mma_kernel<0>, cudaFuncAttributeMaxDynamicSharedMemorySize, SMEM_BYTES);
    cudaFuncSetAttribute(mma_kernel<1>, cudaFuncAttributeMaxDynamicSharedMemorySize, SMEM_BYTES);
    cudaFuncSetAttribute(mma_kernel<2>, cudaFuncAttributeMaxDynamicSharedMemorySize, SMEM_BYTES);

    round_x_kernel<<<MTOT, 256>>>(x);
    transpose_h_kernel<<<dim3(DM/32, DM/32, 1),  dim3(32,8)>>>(Wi, (__half*)pWis, DM, DM, 0, 0);
    transpose_h_kernel<<<dim3(DF/32, DM/32, NH), dim3(32,8)>>>(W1, (__half*)pW1s, DM, DF,
                                                               (size_t)DM*DF, (size_t)DF*DM);
    transpose_h_kernel<<<dim3(DM/32, DF/32, NH), dim3(32,8)>>>(W2, (__half*)pW2s, DF, DM,
                                                               (size_t)DF*DM, (size_t)DM*DF);
    rsproj_kernel<<<dim3(4, DM/128), 128>>>(rs, Wsm, bs);

    // gating GEMM: gelu(x@Wi + bi + rsproj) -> g_gcomb
    mma_kernel<0><<<dim3(DM/128, MTOT/128), 256, SMEM_BYTES>>>(
        (const __half*)pXs, (const __half*)pWis, bi, (const float*)pRp, (float*)pGc, nullptr);

    logits_kernel<<<MTOT/8, 256>>>(Wg, bg, out + (size_t)MTOT*DM);

    // GEMM1 all heads: w[t,z]*gelu(x@W1[z] + b1[z]) -> g_Hid (fp16, [t][z*DF+c])
    mma_kernel<1><<<dim3(DF/128, MTOT/128, NH), 256, SMEM_BYTES>>>(
        (const __half*)pXs, (const __half*)pW1s, b1, (const float*)pWts, nullptr, (__half*)pHid);

    // GEMM2 single K-concat GEMM: sum_h (w*hid_h)@W2[h] + sum_h w*b2[h] -> out
    mma_kernel<2><<<dim3(DM/128, MTOT/128), 256, SMEM_BYTES>>>(
        (const __half*)pHid, (const __half*)pW2s, b2, (const float*)pWts, out, nullptr);
}

// round 16
// speedup vs baseline: 1.0627x; 1.0627x over previous
#include <cuda_runtime.h>
#include <cuda_fp16.h>
#include <cstdint>

#define MTOT 8192
#define DM   1024
#define DF   4096
#define NH   8

#define LDS_   72                        // smem row stride (elems), 144B
#define SLOT_  (128*LDS_)                // one 128x64 tile (elems)
#define SMEM_BYTES (6*SLOT_*2)           // 3 A slots + 3 B slots = 110592
#define SROW   136                       // staging row stride (halfs)

static __device__ __align__(256) __half g_Xs  [(size_t)MTOT*DM];      // x rounded to fp16
static __device__ __align__(256) __half g_Wis [(size_t)DM*DM];
static __device__ __align__(256) __half g_W1s [(size_t)NH*DF*DM];
static __device__ __align__(256) __half g_W2s [(size_t)NH*DM*DF];
static __device__ __align__(256) __half g_Hid [(size_t)MTOT*NH*DF];   // [t][h*DF+c], w-weighted
static __device__ __align__(256) float g_gcomb[(size_t)MTOT*DM];
static __device__ __align__(256) float g_rsproj[4*DM];
static __device__ __align__(256) float g_wts[MTOT*NH];

// ---------------- helpers ----------------
__device__ __forceinline__ uint32_t smem_u32(const void* p){
    uint32_t a;
    asm("{ .reg .u64 t; cvta.to.shared.u64 t, %1; cvt.u32.u64 %0, t; }" : "=r"(a) : "l"(p));
    return a;
}
__device__ __forceinline__ float gelu_f(float v){
    return 0.5f * v * (1.0f + erff(v * 0.7071067811865476f));
}
__device__ __forceinline__ void ldm4(uint32_t* r, uint32_t addr){
    asm volatile("ldmatrix.sync.aligned.m8n8.x4.shared.b16 {%0,%1,%2,%3}, [%4];"
                 : "=r"(r[0]), "=r"(r[1]), "=r"(r[2]), "=r"(r[3]) : "r"(addr));
}
__device__ __forceinline__ void mma_f16(float* d, const uint32_t* a, uint32_t b0, uint32_t b1){
    asm volatile("mma.sync.aligned.m16n8k16.row.col.f32.f16.f16.f32 "
                 "{%0,%1,%2,%3}, {%4,%5,%6,%7}, {%8,%9}, {%0,%1,%2,%3};"
                 : "+f"(d[0]), "+f"(d[1]), "+f"(d[2]), "+f"(d[3])
                 : "r"(a[0]), "r"(a[1]), "r"(a[2]), "r"(a[3]), "r"(b0), "r"(b1));
}
#define CP16(dst, src) asm volatile("cp.async.cg.shared.global [%0], [%1], 16;" :: "r"(dst), "l"(src))
#define CP_COMMIT()    asm volatile("cp.async.commit_group;")
#define CP_WAIT1()     asm volatile("cp.async.wait_group 1;" ::: "memory")
#define CP_WAIT0()     asm volatile("cp.async.wait_group 0;" ::: "memory")

// ---------------- prep kernels ----------------
__global__ void round_x_kernel(const float* __restrict__ x){
    const int t = blockIdx.x;
    const float* xr = x + (size_t)t*DM;
    __half* o = g_Xs + (size_t)t*DM;
    for (int k = threadIdx.x; k < DM; k += 256)
        o[k] = __float2half_rn(xr[k]);
}

// W[K,N] fp32 -> Ws[N,K] fp16; 64-wide K tiles, half2 coalesced writes
__global__ void transpose_h_kernel(const float* __restrict__ W, __half* __restrict__ Ws,
                                   int K, int N, size_t inStride, size_t outStride){
    __shared__ float tile[64][33];
    const float* Wm = W + inStride * blockIdx.z;
    __half* Om = Ws + outStride * blockIdx.z;
    const int n0 = blockIdx.x*32, k0 = blockIdx.y*64;
    const int tx = threadIdx.x, ty = threadIdx.y;
    for (int i = ty; i < 64; i += 8)
        tile[i][tx] = Wm[(size_t)(k0+i)*N + n0 + tx];
    __syncthreads();
    for (int i = ty; i < 32; i += 8){
        const int n = n0 + i;
        __half2 v;
        v.x = __float2half_rn(tile[2*tx][i]);
        v.y = __float2half_rn(tile[2*tx+1][i]);
        *reinterpret_cast<__half2*>(Om + (size_t)n*K + k0 + 2*tx) = v;
    }
}

__global__ void rsproj_kernel(const float* __restrict__ rs, const float* __restrict__ Wsm,
                              const float* __restrict__ bs){
    __shared__ float srs[DM];
    const int b = blockIdx.x;
    const int n = blockIdx.y*128 + threadIdx.x;
    for (int i = threadIdx.x; i < DM; i += 128) srs[i] = rs[(size_t)b*DM + i];
    __syncthreads();
    float acc = bs[n];
    for (int k = 0; k < DM; k++) acc = fmaf(srs[k], Wsm[(size_t)k*DM + n], acc);
    g_rsproj[b*DM + n] = acc;
}

__global__ void logits_kernel(const float* __restrict__ Wg, const float* __restrict__ bg,
                              float* __restrict__ wout){
    __shared__ float sW[NH][DM];
    const int tid = threadIdx.x;
    for (int i = tid; i < DM*NH; i += 256) sW[i & (NH-1)][i >> 3] = Wg[i];
    __syncthreads();
    const int warp = tid >> 5, lid = tid & 31;
    const int t = blockIdx.x*8 + warp;
    const float* g = g_gcomb + (size_t)t*DM;
    float a[NH];
    #pragma unroll
    for (int h = 0; h < NH; h++) a[h] = 0.f;
    for (int k = lid; k < DM; k += 32){
        const float gv = g[k];
        #pragma unroll
        for (int h = 0; h < NH; h++) a[h] = fmaf(gv, sW[h][k], a[h]);
    }
    #pragma unroll
    for (int h = 0; h < NH; h++)
        #pragma unroll
        for (int o = 16; o > 0; o >>= 1)
            a[h] += __shfl_xor_sync(0xFFFFFFFFu, a[h], o);
    if (lid == 0){
        float mx = -1e30f;
        #pragma unroll
        for (int h = 0; h < NH; h++){ a[h] += bg[h]; mx = fmaxf(mx, a[h]); }
        float s = 0.f;
        #pragma unroll
        for (int h = 0; h < NH; h++){ a[h] = expf(a[h]-mx); s += a[h]; }
        const float inv = 1.f/s;
        #pragma unroll
        for (int h = 0; h < NH; h++){
            const float w = a[h]*inv;
            g_wts[t*NH + h] = w;
            wout[t*NH + h]  = w;
        }
    }
}

// ---------------- GEMM: 128x128 CTA tile, 8 warps (2m x 4n), 64x32 warp tile ----------------
// Mainloop identical to the R14 winner. EPI1 output staged through SMEM for 16B stores.
template<int EPI>
__global__ __launch_bounds__(256)
void mma_kernel(const __half* __restrict__ A,
                const __half* __restrict__ B,
                const float* __restrict__ bias,
                const float* __restrict__ extra,
                float* __restrict__ outF,
                __half* __restrict__ outS)
{
    constexpr int RSA = (EPI == 2) ? NH*DF : DM;      // A row stride (elems)
    constexpr int RSB = (EPI == 2) ? DF    : DM;      // B row stride (elems)
    constexpr int NCH = (EPI == 2) ? (NH*DF/64) : (DM/64);   // 512 or 16

    extern __shared__ __align__(16) __half sm[];
    __half* smA = sm;                     // 3 slots
    __half* smB = sm + 3*SLOT_;           // 3 slots

    const int tid = threadIdx.x;
    const int wid = tid >> 5, lane = tid & 31;
    const int wm = wid >> 2, wn = wid & 3;
    const int m0 = blockIdx.y * 128, n0 = blockIdx.x * 128;
    const int z  = blockIdx.z;

    const __half* Bk = B;
    const float*  biask = bias;
    if (EPI == 1){
        Bk    = B + (size_t)z * DF * DM;
        biask = bias + (size_t)z * DF;
    }

    const int grow = tid >> 3;          // 0..31
    const int gcol = (tid & 7) * 8;     // 0,8,...,56

    float acc[4][4][4];
    #pragma unroll
    for (int i = 0; i < 4; i++)
        #pragma unroll
        for (int j = 0; j < 4; j++)
            #pragma unroll
            for (int r = 0; r < 4; r++) acc[i][j][r] = 0.f;

    auto load_stage = [&](int kc){
        __half* sa = smA + (kc % 3) * SLOT_;
        __half* sb = smB + (kc % 3) * SLOT_;
        const size_t koA = (size_t)kc * 64;
        size_t baseB;
        if (EPI == 2){
            const int hB = kc >> 6;                   // DF/64 = 64 chunks/head
            baseB = (size_t)hB * DM * DF + (size_t)(kc & 63) * 64;
        } else {
            baseB = (size_t)kc * 64;
        }
        #pragma unroll
        for (int r = 0; r < 4; r++){
            const int row = grow + r*32;
            CP16(smem_u32(sa + (size_t)row*LDS_ + gcol),
                 A + (size_t)(m0 + row)*RSA + koA + gcol);
            CP16(smem_u32(sb + (size_t)row*LDS_ + gcol),
                 Bk + baseB + (size_t)(n0 + row)*RSB + gcol);
        }
        CP_COMMIT();
    };

    load_stage(0);
    load_stage(1);

    for (int kc = 0; kc < NCH; kc++){
        CP_WAIT1();
        __syncthreads();
        const __half* sa = smA + (kc % 3) * SLOT_;
        const __half* sb = smB + (kc % 3) * SLOT_;
        const uint32_t abase = smem_u32(sa + ((size_t)(wm*64 + (lane & 15)))*LDS_ + (lane >> 4)*8);
        const uint32_t bbase = smem_u32(sb + ((size_t)(wn*32 + (lane & 15)))*LDS_ + (lane >> 4)*8);
        #pragma unroll
        for (int kk = 0; kk < 4; kk++){
            uint32_t af[4][4], bf[2][4];
            #pragma unroll
            for (int mt = 0; mt < 4; mt++)
                ldm4(af[mt], abase + (uint32_t)(mt*16*LDS_)*2 + kk*32);
            #pragma unroll
            for (int g = 0; g < 2; g++)
                ldm4(bf[g], bbase + (uint32_t)(g*16*LDS_)*2 + kk*32);
            #pragma unroll
            for (int mt = 0; mt < 4; mt++)
                #pragma unroll
                for (int nt = 0; nt < 4; nt++)
                    mma_f16(acc[mt][nt], af[mt], bf[nt>>1][nt&1], bf[nt>>1][2 + (nt&1)]);
        }
        if (kc + 2 < NCH) load_stage(kc + 2);
        else CP_COMMIT();
    }

    // post-mainloop SMEM reuse (EPI1 staging / EPI2 bias): drain & sync first
    float* sB2 = (float*)sm;
    __half* sStg = sm;                    // 128 x SROW halfs = 34 KB (fits in A slots)
    if (EPI == 1 || EPI == 2){
        CP_WAIT0();
        __syncthreads();
        if (EPI == 2){
            for (int i = tid; i < NH*128; i += 256)
                sB2[i] = bias[(i >> 7)*DM + n0 + (i & 127)];
            __syncthreads();
        }
    }

    // -------- epilogue --------
    const int lr = lane >> 2, lc = 2 * (lane & 3);
    #pragma unroll
    for (int mt = 0; mt < 4; mt++){
        #pragma unroll
        for (int half = 0; half < 2; half++){
            const int tl = wm*64 + mt*16 + lr + 8*half;   // local row 0..127
            const int t = m0 + tl;
            float wv[NH];
            if (EPI == 2){
                const float* wr = extra + t*NH;
                #pragma unroll
                for (int h = 0; h < NH; h++) wv[h] = wr[h];
            }
            float gw = 0.f;
            if (EPI == 1) gw = extra[t*NH + z];
            #pragma unroll
            for (int nt = 0; nt < 4; nt++){
                const int cl = wn*32 + nt*8 + lc;         // local col 0..127
                const int c = n0 + cl;
                float v0 = acc[mt][nt][2*half];
                float v1 = acc[mt][nt][2*half + 1];
                if (EPI == 0){
                    const float* rp = extra + (size_t)(t >> 11)*DM;
                    float2 o;
                    o.x = gelu_f(v0 + biask[c]   + rp[c]);
                    o.y = gelu_f(v1 + biask[c+1] + rp[c+1]);
                    *reinterpret_cast<float2*>(outF + (size_t)t*DM + c) = o;
                } else if (EPI == 1){
                    v0 = gw * gelu_f(v0 + biask[c]);
                    v1 = gw * gelu_f(v1 + biask[c+1]);
                    __half2 ph;
                    ph.x = __float2half_rn(v0); ph.y = __float2half_rn(v1);
                    *reinterpret_cast<__half2*>(sStg + (size_t)tl*SROW + cl) = ph;
                } else {
                    float b0 = 0.f, b1v = 0.f;
                    #pragma unroll
                    for (int h = 0; h < NH; h++){
                        b0  = fmaf(wv[h], sB2[h*128 + cl],     b0);
                        b1v = fmaf(wv[h], sB2[h*128 + cl + 1], b1v);
                    }
                    float2 o; o.x = v0 + b0; o.y = v1 + b1v;
                    *reinterpret_cast<float2*>(outF + (size_t)t*DM + c) = o;
                }
            }
        }
    }

    if (EPI == 1){
        __syncthreads();
        // coalesced copy: 128 rows x 128 halfs; 16 uint4 per row, 2048 total / 256 thr = 8 each
        #pragma unroll
        for (int it = 0; it < 8; it++){
            const int idx = tid + it*256;
            const int row = idx >> 4, seg = idx & 15;
            const uint4 v = *reinterpret_cast<const uint4*>(sStg + (size_t)row*SROW + seg*8);
            *reinterpret_cast<uint4*>(outS + (size_t)(m0 + row)*NH*DF + (size_t)z*DF + n0 + seg*8) = v;
        }
    }
}

// ---------------- host ----------------
extern "C" void kernel_launch(void* const* d_in, const int* in_sizes, int n_in,
                              void* d_out, int out_size){
    const float* x   = (const float*)d_in[0];
    const float* rs  = (const float*)d_in[1];
    const float* W1  = (const float*)d_in[2];
    const float* b1  = (const float*)d_in[3];
    const float* W2  = (const float*)d_in[4];
    const float* b2  = (const float*)d_in[5];
    const float* Wsm = (const float*)d_in[6];
    const float* bs  = (const float*)d_in[7];
    const float* Wi  = (const float*)d_in[8];
    const float* bi  = (const float*)d_in[9];
    const float* Wg  = (const float*)d_in[10];
    const float* bg  = (const float*)d_in[11];
    float* out = (float*)d_out;

    void *pXs,*pWis,*pW1s,*pW2s,*pHid,*pGc,*pRp,*pWts;
    cudaGetSymbolAddress(&pXs,  g_Xs);
    cudaGetSymbolAddress(&pWis, g_Wis);
    cudaGetSymbolAddress(&pW1s, g_W1s);
    cudaGetSymbolAddress(&pW2s, g_W2s);
    cudaGetSymbolAddress(&pHid, g_Hid);
    cudaGetSymbolAddress(&pGc,  g_gcomb);
    cudaGetSymbolAddress(&pRp,  g_rsproj);
    cudaGetSymbolAddress(&pWts, g_wts);

    cudaFuncSetAttribute(mma_kernel<0>, cudaFuncAttributeMaxDynamicSharedMemorySize, SMEM_BYTES);
    cudaFuncSetAttribute(mma_kernel<1>, cudaFuncAttributeMaxDynamicSharedMemorySize, SMEM_BYTES);
    cudaFuncSetAttribute(mma_kernel<2>, cudaFuncAttributeMaxDynamicSharedMemorySize, SMEM_BYTES);

    round_x_kernel<<<MTOT, 256>>>(x);
    transpose_h_kernel<<<dim3(DM/32, DM/64, 1),  dim3(32,8)>>>(Wi, (__half*)pWis, DM, DM, 0, 0);
    transpose_h_kernel<<<dim3(DF/32, DM/64, NH), dim3(32,8)>>>(W1, (__half*)pW1s, DM, DF,
                                                               (size_t)DM*DF, (size_t)DF*DM);
    transpose_h_kernel<<<dim3(DM/32, DF/64, NH), dim3(32,8)>>>(W2, (__half*)pW2s, DF, DM,
                                                               (size_t)DF*DM, (size_t)DM*DF);
    rsproj_kernel<<<dim3(4, DM/128), 128>>>(rs, Wsm, bs);

    // gating GEMM: gelu(x@Wi + bi + rsproj) -> g_gcomb
    mma_kernel<0><<<dim3(DM/128, MTOT/128), 256, SMEM_BYTES>>>(
        (const __half*)pXs, (const __half*)pWis, bi, (const float*)pRp, (float*)pGc, nullptr);

    logits_kernel<<<MTOT/8, 256>>>(Wg, bg, out + (size_t)MTOT*DM);

    // GEMM1 all heads: w[t,z]*gelu(x@W1[z] + b1[z]) -> g_Hid (fp16, [t][z*DF+c])
    mma_kernel<1><<<dim3(DF/128, MTOT/128, NH), 256, SMEM_BYTES>>>(
        (const __half*)pXs, (const __half*)pW1s, b1, (const float*)pWts, nullptr, (__half*)pHid);

    // GEMM2 single K-concat GEMM: sum_h (w*hid_h)@W2[h] + sum_h w*b2[h] -> out
    mma_kernel<2><<<dim3(DM/128, MTOT/128), 256, SMEM_BYTES>>>(
        (const __half*)pHid, (const __half*)pW2s, b2, (const float*)pWts, out, nullptr);
}